// round 1
// baseline (speedup 1.0000x reference)
#include <cuda_runtime.h>

#define NB 4
#define NN 900
#define ND 256
#define NV 16
#define NH 8

__device__ __forceinline__ float fast_ex2(float x) {
    float r; asm("ex2.approx.ftz.f32 %0, %1;" : "=f"(r) : "f"(x)); return r;
}
__device__ __forceinline__ float fast_sin(float x) {
    float r; asm("sin.approx.ftz.f32 %0, %1;" : "=f"(r) : "f"(x)); return r;
}
__device__ __forceinline__ float fast_cos(float x) {
    float r; asm("cos.approx.ftz.f32 %0, %1;" : "=f"(r) : "f"(x)); return r;
}

// One block per (b, n) row. 256 threads.
// Fuses: votes GEMM row, vote_pos, sigma table, score row (sum over V of exp),
// row normalization, sine positional embedding, 8-head projection + ReLU.
__global__ __launch_bounds__(256, 1)
void hough_fused_kernel(const float* __restrict__ q,     // (B,N,D)
                        const float* __restrict__ cur,   // (B,N,4)
                        const float* __restrict__ vw,    // (32,D)
                        const float* __restrict__ vb,    // (32)
                        const float* __restrict__ pw,    // (H,16)
                        const float* __restrict__ pb,    // (H)
                        float* __restrict__ out)         // (B,H,N,N)
{
    const int bn   = blockIdx.x;
    const int b    = bn / NN;
    const int n    = bn % NN;
    const int tid  = threadIdx.x;
    const int lane = tid & 31;
    const int w    = tid >> 5;

    __shared__ float  sq[ND];        // query row
    __shared__ float2 sC[NN];        // centers (x,y)
    __shared__ float  sI[NN];        // imap row (un-normalized)
    __shared__ float2 sV[NV];        // vote positions
    __shared__ float  sVV[NV];       // |vote|^2
    __shared__ float  sNinv[NV];     // -8*log2(e)/(c2+c3)^2  (== -log2(e)/(2 sigma^2))
    __shared__ float  sW[NH * 16];   // proj_w
    __shared__ float  sB[NH];        // proj_b
    __shared__ float  sVotes[2 * NV];
    __shared__ float  sRed[8];
    __shared__ float  sInvZ;

    // ---- loads ----
    sq[tid] = q[bn * ND + tid];
    for (int j = tid; j < NN; j += 256) {
        float4 c4 = *reinterpret_cast<const float4*>(cur + (b * NN + j) * 4);
        sC[j] = make_float2(c4.x, c4.y);
    }
    if (tid < NH * 16) sW[tid] = pw[tid];
    if (tid < NH)      sB[tid] = pb[tid];
    __syncthreads();

    // ---- votes = q_row @ vote_w.T + vote_b : 8 warps x 4 outputs ----
    {
        const int k0 = w * 4;
        const float* w0 = vw + (k0 + 0) * ND;
        const float* w1 = vw + (k0 + 1) * ND;
        const float* w2 = vw + (k0 + 2) * ND;
        const float* w3 = vw + (k0 + 3) * ND;
        float a0 = 0.f, a1 = 0.f, a2 = 0.f, a3 = 0.f;
        #pragma unroll
        for (int i = 0; i < 8; i++) {
            int d = lane + 32 * i;
            float qv = sq[d];
            a0 = fmaf(qv, __ldg(w0 + d), a0);
            a1 = fmaf(qv, __ldg(w1 + d), a1);
            a2 = fmaf(qv, __ldg(w2 + d), a2);
            a3 = fmaf(qv, __ldg(w3 + d), a3);
        }
        #pragma unroll
        for (int o = 16; o; o >>= 1) {
            a0 += __shfl_down_sync(0xffffffffu, a0, o);
            a1 += __shfl_down_sync(0xffffffffu, a1, o);
            a2 += __shfl_down_sync(0xffffffffu, a2, o);
            a3 += __shfl_down_sync(0xffffffffu, a3, o);
        }
        if (lane == 0) {
            sVotes[k0 + 0] = a0 + vb[k0 + 0];
            sVotes[k0 + 1] = a1 + vb[k0 + 1];
            sVotes[k0 + 2] = a2 + vb[k0 + 2];
            sVotes[k0 + 3] = a3 + vb[k0 + 3];
        }
    }
    __syncthreads();

    // ---- vote positions + sigma coefficients ----
    if (tid < NV) {
        float cx = cur[bn * 4 + 0];
        float cy = cur[bn * 4 + 1];
        float vx = cx + sVotes[2 * tid + 0];
        float vy = cy + sVotes[2 * tid + 1];
        sV[tid]  = make_float2(vx, vy);
        sVV[tid] = fmaf(vx, vx, vy * vy);
        // reference quirk: sigma_flat index is (n*V + v) mod N
        int idx  = (n * NV + tid) % NN;
        float c2 = cur[(b * NN + idx) * 4 + 2];
        float c3 = cur[(b * NN + idx) * 4 + 3];
        float s  = c2 + c3;                    // 4*sigma
        // exp(-d2/(2*sigma^2)) = 2^( d2 * (-8*log2e / s^2) )
        sNinv[tid] = -11.541560327111707f / (s * s);
    }
    __syncthreads();

    // ---- pass 1: imap row = sum_v exp(...) ----
    float part = 0.f;
    for (int m = tid; m < NN; m += 256) {
        float2 c  = sC[m];
        float  cc = fmaf(c.x, c.x, c.y * c.y);
        float acc = 0.f;
        #pragma unroll
        for (int v = 0; v < NV; v++) {
            float2 vp  = sV[v];
            float  dot = fmaf(vp.x, c.x, vp.y * c.y);
            float  d2  = fmaf(-2.f, dot, sVV[v] + cc);
            d2 = fmaxf(d2, 0.f);
            acc += fast_ex2(d2 * sNinv[v]);
        }
        sI[m] = acc;
        part += acc;
    }
    // block reduce (all values positive -> abs is identity)
    #pragma unroll
    for (int o = 16; o; o >>= 1) part += __shfl_down_sync(0xffffffffu, part, o);
    if (lane == 0) sRed[w] = part;
    __syncthreads();
    if (tid == 0) {
        float t = 0.f;
        #pragma unroll
        for (int i = 0; i < 8; i++) t += sRed[i];
        sInvZ = 1.f / fmaxf(t, 1e-12f);
    }
    __syncthreads();
    const float invZ = sInvZ;

    // 100 / 10000^(j/8)
    const float SCJ[8] = {100.f, 31.622776601683793f, 10.f, 3.1622776601683795f,
                          1.f, 0.31622776601683794f, 0.1f, 0.031622776601683794f};

    // ---- pass 2: sine embed + 8-head projection + relu ----
    for (int m = tid; m < NN; m += 256) {
        float x = 1.f - sI[m] * invZ;
        float sv[8], cv[8];
        #pragma unroll
        for (int j = 0; j < 8; j++) {
            float t = x * SCJ[j];
            sv[j] = fast_sin(t);
            cv[j] = fast_cos(t);
        }
        int obase = ((b * NH) * NN + n) * NN + m;
        #pragma unroll
        for (int h = 0; h < NH; h++) {
            float o = sB[h];
            #pragma unroll
            for (int j = 0; j < 8; j++) {
                o = fmaf(sv[j], sW[h * 16 + 2 * j + 0], o);
                o = fmaf(cv[j], sW[h * 16 + 2 * j + 1], o);
            }
            out[obase + h * (NN * NN)] = fmaxf(o, 0.f);
        }
    }
}

extern "C" void kernel_launch(void* const* d_in, const int* in_sizes, int n_in,
                              void* d_out, int out_size) {
    const float* queries = (const float*)d_in[0];
    const float* cur_ref = (const float*)d_in[1];
    // d_in[2] = prev_ref_points — unused by the reference
    const float* vote_w  = (const float*)d_in[3];
    const float* vote_b  = (const float*)d_in[4];
    const float* proj_w  = (const float*)d_in[5];
    const float* proj_b  = (const float*)d_in[6];
    float* out = (float*)d_out;

    hough_fused_kernel<<<NB * NN, 256>>>(queries, cur_ref, vote_w, vote_b,
                                         proj_w, proj_b, out);
}

// round 2
// speedup vs baseline: 1.1767x; 1.1767x over previous
#include <cuda_runtime.h>

#define NB 4
#define NN 900
#define ND 256
#define NV 16
#define NH 8
#define NN2 (NN * NN)

// scratch: x = 1 - imap/Z, laid out (B,N,N) contiguous
__device__ float g_x[NB * NN2];

__device__ __forceinline__ float fast_ex2(float x) {
    float r; asm("ex2.approx.ftz.f32 %0, %1;" : "=f"(r) : "f"(x)); return r;
}
__device__ __forceinline__ float fast_sin(float x) {
    float r; asm("sin.approx.ftz.f32 %0, %1;" : "=f"(r) : "f"(x)); return r;
}
__device__ __forceinline__ float fast_cos(float x) {
    float r; asm("cos.approx.ftz.f32 %0, %1;" : "=f"(r) : "f"(x)); return r;
}
__device__ __forceinline__ unsigned long long pack2(float a, float b) {
    unsigned long long r;
    asm("mov.b64 %0, {%1, %2};" : "=l"(r)
        : "r"(__float_as_uint(a)), "r"(__float_as_uint(b)));
    return r;
}
__device__ __forceinline__ float2 unpack2(unsigned long long v) {
    unsigned int lo, hi;
    asm("mov.b64 {%0, %1}, %2;" : "=r"(lo), "=r"(hi) : "l"(v));
    return make_float2(__uint_as_float(lo), __uint_as_float(hi));
}
__device__ __forceinline__ unsigned long long fma2(unsigned long long a,
                                                   unsigned long long b,
                                                   unsigned long long c) {
    unsigned long long d;
    asm("fma.rn.f32x2 %0, %1, %2, %3;" : "=l"(d) : "l"(a), "l"(b), "l"(c));
    return d;
}

// ---------------------------------------------------------------------------
// Kernel A: one block per (b,n) row. votes GEMM + scores + row normalization.
// Writes x = 1 - imap/Z into g_x.
// ---------------------------------------------------------------------------
__global__ __launch_bounds__(256, 2)
void hough_row_kernel(const float* __restrict__ q,     // (B,N,D)
                      const float* __restrict__ cur,   // (B,N,4)
                      const float* __restrict__ vw,    // (32,D)
                      const float* __restrict__ vb)    // (32)
{
    const int bn   = blockIdx.x;
    const int b    = bn / NN;
    const int n    = bn % NN;
    const int tid  = threadIdx.x;
    const int lane = tid & 31;
    const int w    = tid >> 5;

    __shared__ float  sq[ND];
    __shared__ float2 sC[NN];
    __shared__ float  sI[NN];
    __shared__ float2 sV[NV];
    __shared__ float  sVV[NV];
    __shared__ float  sNinv[NV];
    __shared__ float  sVotes[2 * NV];
    __shared__ float  sRed[8];
    __shared__ float  sInvZ;

    sq[tid] = q[bn * ND + tid];
    for (int j = tid; j < NN; j += 256) {
        float4 c4 = *reinterpret_cast<const float4*>(cur + (b * NN + j) * 4);
        sC[j] = make_float2(c4.x, c4.y);
    }
    __syncthreads();

    // votes = q_row @ vote_w.T + vote_b  (8 warps x 4 outputs)
    {
        const int k0 = w * 4;
        const float* w0 = vw + (k0 + 0) * ND;
        const float* w1 = vw + (k0 + 1) * ND;
        const float* w2 = vw + (k0 + 2) * ND;
        const float* w3 = vw + (k0 + 3) * ND;
        float a0 = 0.f, a1 = 0.f, a2 = 0.f, a3 = 0.f;
        #pragma unroll
        for (int i = 0; i < 8; i++) {
            int d = lane + 32 * i;
            float qv = sq[d];
            a0 = fmaf(qv, __ldg(w0 + d), a0);
            a1 = fmaf(qv, __ldg(w1 + d), a1);
            a2 = fmaf(qv, __ldg(w2 + d), a2);
            a3 = fmaf(qv, __ldg(w3 + d), a3);
        }
        #pragma unroll
        for (int o = 16; o; o >>= 1) {
            a0 += __shfl_down_sync(0xffffffffu, a0, o);
            a1 += __shfl_down_sync(0xffffffffu, a1, o);
            a2 += __shfl_down_sync(0xffffffffu, a2, o);
            a3 += __shfl_down_sync(0xffffffffu, a3, o);
        }
        if (lane == 0) {
            sVotes[k0 + 0] = a0 + vb[k0 + 0];
            sVotes[k0 + 1] = a1 + vb[k0 + 1];
            sVotes[k0 + 2] = a2 + vb[k0 + 2];
            sVotes[k0 + 3] = a3 + vb[k0 + 3];
        }
    }
    __syncthreads();

    if (tid < NV) {
        float cx = cur[bn * 4 + 0];
        float cy = cur[bn * 4 + 1];
        float vx = cx + sVotes[2 * tid + 0];
        float vy = cy + sVotes[2 * tid + 1];
        sV[tid]  = make_float2(vx, vy);
        sVV[tid] = fmaf(vx, vx, vy * vy);
        // reference quirk: sigma index is (n*V + v) mod N
        int idx  = (n * NV + tid) % NN;
        float c2 = cur[(b * NN + idx) * 4 + 2];
        float c3 = cur[(b * NN + idx) * 4 + 3];
        float s  = c2 + c3;   // 4*sigma
        // exp(-d2/(2 sigma^2)) = 2^( d2 * (-8*log2e / s^2) )
        sNinv[tid] = -11.541560327111707f / (s * s);
    }
    __syncthreads();

    float part = 0.f;
    for (int m = tid; m < NN; m += 256) {
        float2 c  = sC[m];
        float  cc = fmaf(c.x, c.x, c.y * c.y);
        float acc = 0.f;
        #pragma unroll
        for (int v = 0; v < NV; v++) {
            float2 vp  = sV[v];
            float  dot = fmaf(vp.x, c.x, vp.y * c.y);
            float  d2  = fmaf(-2.f, dot, sVV[v] + cc);
            d2 = fmaxf(d2, 0.f);
            acc += fast_ex2(d2 * sNinv[v]);
        }
        sI[m] = acc;
        part += acc;
    }
    #pragma unroll
    for (int o = 16; o; o >>= 1) part += __shfl_down_sync(0xffffffffu, part, o);
    if (lane == 0) sRed[w] = part;
    __syncthreads();
    if (tid == 0) {
        float t = 0.f;
        #pragma unroll
        for (int i = 0; i < 8; i++) t += sRed[i];
        sInvZ = 1.f / fmaxf(t, 1e-12f);
    }
    __syncthreads();
    const float invZ = sInvZ;

    float* xr = g_x + (size_t)bn * NN;
    for (int m = tid; m < NN; m += 256)
        xr[m] = 1.f - sI[m] * invZ;
}

// ---------------------------------------------------------------------------
// Kernel B: elementwise sine embed + 8-head projection (f32x2 packed) + ReLU.
// blockIdx.y = batch, blockIdx.x strides over the N*N plane.
// ---------------------------------------------------------------------------
__global__ __launch_bounds__(256, 3)
void embed_proj_kernel(const float* __restrict__ pw,   // (H,16)
                       const float* __restrict__ pb,   // (H)
                       float* __restrict__ out)        // (B,H,N,N)
{
    // packed head-pair weights: sWp[p][k] = (W[2p][k], W[2p+1][k])
    __shared__ unsigned long long sWp[4][16];
    __shared__ unsigned long long sBp[4];

    const int tid = threadIdx.x;
    if (tid < 64) {
        int p = tid >> 4, k = tid & 15;
        sWp[p][k] = pack2(pw[(2 * p) * 16 + k], pw[(2 * p + 1) * 16 + k]);
    }
    if (tid < 4) sBp[tid] = pack2(pb[2 * tid], pb[2 * tid + 1]);
    __syncthreads();

    const int b = blockIdx.y;
    const int r = blockIdx.x * 256 + tid;   // index within the N*N plane
    if (r >= NN2) return;

    const float xv = g_x[(size_t)b * NN2 + r];

    // 100 / 10000^(j/8)
    const float SCJ[8] = {100.f, 31.622776601683793f, 10.f, 3.1622776601683795f,
                          1.f, 0.31622776601683794f, 0.1f, 0.031622776601683794f};

    unsigned long long f[16];   // feature duplicated in both f32x2 lanes
    #pragma unroll
    for (int j = 0; j < 8; j++) {
        float t = xv * SCJ[j];
        float s = fast_sin(t);
        float c = fast_cos(t);
        f[2 * j + 0] = pack2(s, s);
        f[2 * j + 1] = pack2(c, c);
    }

    float* obase = out + ((size_t)b * NH) * NN2 + r;
    #pragma unroll
    for (int p = 0; p < 4; p++) {
        unsigned long long acc = sBp[p];
        #pragma unroll
        for (int k = 0; k < 16; k++)
            acc = fma2(f[k], sWp[p][k], acc);
        float2 o = unpack2(acc);
        obase[(2 * p + 0) * NN2] = fmaxf(o.x, 0.f);
        obase[(2 * p + 1) * NN2] = fmaxf(o.y, 0.f);
    }
}

extern "C" void kernel_launch(void* const* d_in, const int* in_sizes, int n_in,
                              void* d_out, int out_size) {
    const float* queries = (const float*)d_in[0];
    const float* cur_ref = (const float*)d_in[1];
    // d_in[2] = prev_ref_points — unused by the reference
    const float* vote_w  = (const float*)d_in[3];
    const float* vote_b  = (const float*)d_in[4];
    const float* proj_w  = (const float*)d_in[5];
    const float* proj_b  = (const float*)d_in[6];
    float* out = (float*)d_out;

    hough_row_kernel<<<NB * NN, 256>>>(queries, cur_ref, vote_w, vote_b);

    dim3 gridB((NN2 + 255) / 256, NB);
    embed_proj_kernel<<<gridB, 256>>>(proj_w, proj_b, out);
}

// round 3
// speedup vs baseline: 1.4609x; 1.2415x over previous
#include <cuda_runtime.h>

#define NB 4
#define NN 900
#define ND 256
#define NV 16
#define NH 8
#define NN2 (NN * NN)

// scratch: x = 1 - imap/Z, laid out (B,N,N) contiguous
__device__ float g_x[NB * NN2];

__device__ __forceinline__ float fast_ex2(float x) {
    float r; asm("ex2.approx.ftz.f32 %0, %1;" : "=f"(r) : "f"(x)); return r;
}
__device__ __forceinline__ float fast_sin(float x) {
    float r; asm("sin.approx.ftz.f32 %0, %1;" : "=f"(r) : "f"(x)); return r;
}
__device__ __forceinline__ float fast_cos(float x) {
    float r; asm("cos.approx.ftz.f32 %0, %1;" : "=f"(r) : "f"(x)); return r;
}
__device__ __forceinline__ unsigned long long pack2(float a, float b) {
    unsigned long long r;
    asm("mov.b64 %0, {%1, %2};" : "=l"(r)
        : "r"(__float_as_uint(a)), "r"(__float_as_uint(b)));
    return r;
}
__device__ __forceinline__ float2 unpack2(unsigned long long v) {
    unsigned int lo, hi;
    asm("mov.b64 {%0, %1}, %2;" : "=r"(lo), "=r"(hi) : "l"(v));
    return make_float2(__uint_as_float(lo), __uint_as_float(hi));
}
__device__ __forceinline__ unsigned long long fma2(unsigned long long a,
                                                   unsigned long long b,
                                                   unsigned long long c) {
    unsigned long long d;
    asm("fma.rn.f32x2 %0, %1, %2, %3;" : "=l"(d) : "l"(a), "l"(b), "l"(c));
    return d;
}

// ---------------------------------------------------------------------------
// Kernel A: one block per (b,n) row.
// Warps 0-3 handle votes 0-7, warps 4-7 handle votes 8-15 (registerized
// coefficients, zero shared loads in the inner loop).
// e = ninv*d2 folded: e = Ni*cc + C0 + Ax*cx + Ay*cy, arg = min(e, 0).
// ---------------------------------------------------------------------------
__global__ __launch_bounds__(256, 3)
void hough_row_kernel(const float* __restrict__ q,     // (B,N,D)
                      const float* __restrict__ cur,   // (B,N,4)
                      const float* __restrict__ vw,    // (32,D)
                      const float* __restrict__ vb)    // (32)
{
    const int bn   = blockIdx.x;
    const int b    = bn / NN;
    const int n    = bn % NN;
    const int tid  = threadIdx.x;
    const int lane = tid & 31;
    const int w    = tid >> 5;
    const int g    = tid >> 7;          // vote group 0/1
    const int tg   = tid & 127;         // thread index within group

    __shared__ float  sq[ND];
    __shared__ float2 sC[NN];
    __shared__ float  sI[2][NN];
    __shared__ float4 sCoef[NV];        // (Ax, Ay, Ni, C0)
    __shared__ float  sVotes[2 * NV];
    __shared__ float  sRed[8];
    __shared__ float  sInvZ;

    sq[tid] = q[bn * ND + tid];
    for (int j = tid; j < NN; j += 256) {
        float4 c4 = *reinterpret_cast<const float4*>(cur + (b * NN + j) * 4);
        sC[j] = make_float2(c4.x, c4.y);
    }
    __syncthreads();

    // votes = q_row @ vote_w.T + vote_b  (8 warps x 4 outputs)
    {
        const int k0 = w * 4;
        const float* w0 = vw + (k0 + 0) * ND;
        const float* w1 = vw + (k0 + 1) * ND;
        const float* w2 = vw + (k0 + 2) * ND;
        const float* w3 = vw + (k0 + 3) * ND;
        float a0 = 0.f, a1 = 0.f, a2 = 0.f, a3 = 0.f;
        #pragma unroll
        for (int i = 0; i < 8; i++) {
            int d = lane + 32 * i;
            float qv = sq[d];
            a0 = fmaf(qv, __ldg(w0 + d), a0);
            a1 = fmaf(qv, __ldg(w1 + d), a1);
            a2 = fmaf(qv, __ldg(w2 + d), a2);
            a3 = fmaf(qv, __ldg(w3 + d), a3);
        }
        #pragma unroll
        for (int o = 16; o; o >>= 1) {
            a0 += __shfl_down_sync(0xffffffffu, a0, o);
            a1 += __shfl_down_sync(0xffffffffu, a1, o);
            a2 += __shfl_down_sync(0xffffffffu, a2, o);
            a3 += __shfl_down_sync(0xffffffffu, a3, o);
        }
        if (lane == 0) {
            sVotes[k0 + 0] = a0 + vb[k0 + 0];
            sVotes[k0 + 1] = a1 + vb[k0 + 1];
            sVotes[k0 + 2] = a2 + vb[k0 + 2];
            sVotes[k0 + 3] = a3 + vb[k0 + 3];
        }
    }
    __syncthreads();

    if (tid < NV) {
        float cx = cur[bn * 4 + 0];
        float cy = cur[bn * 4 + 1];
        float vx = cx + sVotes[2 * tid + 0];
        float vy = cy + sVotes[2 * tid + 1];
        // reference quirk: sigma index is (n*V + v) mod N
        int idx  = (n * NV + tid) % NN;
        float c2 = cur[(b * NN + idx) * 4 + 2];
        float c3 = cur[(b * NN + idx) * 4 + 3];
        float s  = c2 + c3;   // 4*sigma
        // exp(-d2/(2 sigma^2)) = 2^(d2 * ninv), ninv = -8*log2e / s^2
        float ninv = -11.541560327111707f / (s * s);
        float vv   = fmaf(vx, vx, vy * vy);
        sCoef[tid] = make_float4(-2.f * ninv * vx,   // Ax
                                 -2.f * ninv * vy,   // Ay
                                 ninv,               // Ni
                                 ninv * vv);         // C0
    }
    __syncthreads();

    // registerize this group's 8 coefficient quads
    float Ax[8], Ay[8], Ni[8], C0[8];
    #pragma unroll
    for (int v = 0; v < 8; v++) {
        float4 c = sCoef[g * 8 + v];
        Ax[v] = c.x; Ay[v] = c.y; Ni[v] = c.z; C0[v] = c.w;
    }

    float part = 0.f;
    for (int m = tg; m < NN; m += 128) {
        float2 c  = sC[m];
        float  cc = fmaf(c.x, c.x, c.y * c.y);
        float acc = 0.f;
        #pragma unroll
        for (int v = 0; v < 8; v++) {
            float e = fmaf(c.x, Ax[v], fmaf(c.y, Ay[v], fmaf(cc, Ni[v], C0[v])));
            acc += fast_ex2(fminf(e, 0.f));
        }
        sI[g][m] = acc;
        part += acc;
    }
    #pragma unroll
    for (int o = 16; o; o >>= 1) part += __shfl_down_sync(0xffffffffu, part, o);
    if (lane == 0) sRed[w] = part;
    __syncthreads();
    if (tid == 0) {
        float t = 0.f;
        #pragma unroll
        for (int i = 0; i < 8; i++) t += sRed[i];
        sInvZ = 1.f / fmaxf(t, 1e-12f);
    }
    __syncthreads();
    const float invZ = sInvZ;

    float* xr = g_x + (size_t)bn * NN;
    for (int m = tid; m < NN; m += 256)
        xr[m] = 1.f - (sI[0][m] + sI[1][m]) * invZ;
}

// ---------------------------------------------------------------------------
// Kernel B: 4 consecutive elements per thread, element-pair f32x2 packing,
// vectorized STG.128 per head. blockIdx.y = batch.
// ---------------------------------------------------------------------------
__global__ __launch_bounds__(256, 2)
void embed_proj_kernel(const float* __restrict__ pw,   // (H,16)
                       const float* __restrict__ pb,   // (H)
                       float* __restrict__ out)        // (B,H,N,N)
{
    __shared__ unsigned long long sWb[NH][16];  // (w,w) duplicated
    __shared__ unsigned long long sBb[NH];      // (b,b) duplicated

    const int tid = threadIdx.x;
    if (tid < NH * 16) {
        int p = tid >> 4, k = tid & 15;
        float wv = pw[p * 16 + k];
        sWb[p][k] = pack2(wv, wv);
    }
    if (tid < NH) sBb[tid] = pack2(pb[tid], pb[tid]);
    __syncthreads();

    const int b  = blockIdx.y;
    const int r4 = (blockIdx.x * 256 + tid) * 4;
    if (r4 >= NN2) return;

    const float4 xv4 = *reinterpret_cast<const float4*>(g_x + (size_t)b * NN2 + r4);
    const float xv[4] = {xv4.x, xv4.y, xv4.z, xv4.w};

    // 100 / 10000^(j/8)
    const float SCJ[8] = {100.f, 31.622776601683793f, 10.f, 3.1622776601683795f,
                          1.f, 0.31622776601683794f, 0.1f, 0.031622776601683794f};

    // f[pair][k]: features for element pair (2p, 2p+1), k even=sin, odd=cos
    unsigned long long f[2][16];
    #pragma unroll
    for (int p = 0; p < 2; p++) {
        #pragma unroll
        for (int j = 0; j < 8; j++) {
            float t0 = xv[2 * p + 0] * SCJ[j];
            float t1 = xv[2 * p + 1] * SCJ[j];
            f[p][2 * j + 0] = pack2(fast_sin(t0), fast_sin(t1));
            f[p][2 * j + 1] = pack2(fast_cos(t0), fast_cos(t1));
        }
    }

    float* obase = out + ((size_t)b * NH) * NN2 + r4;
    #pragma unroll
    for (int h = 0; h < NH; h++) {
        unsigned long long a0 = sBb[h];
        unsigned long long a1 = a0;
        #pragma unroll
        for (int k = 0; k < 16; k++) {
            unsigned long long wv = sWb[h][k];
            a0 = fma2(f[0][k], wv, a0);
            a1 = fma2(f[1][k], wv, a1);
        }
        float2 o0 = unpack2(a0);
        float2 o1 = unpack2(a1);
        float4 o = make_float4(fmaxf(o0.x, 0.f), fmaxf(o0.y, 0.f),
                               fmaxf(o1.x, 0.f), fmaxf(o1.y, 0.f));
        *reinterpret_cast<float4*>(obase + (size_t)h * NN2) = o;
    }
}

extern "C" void kernel_launch(void* const* d_in, const int* in_sizes, int n_in,
                              void* d_out, int out_size) {
    const float* queries = (const float*)d_in[0];
    const float* cur_ref = (const float*)d_in[1];
    // d_in[2] = prev_ref_points — unused by the reference
    const float* vote_w  = (const float*)d_in[3];
    const float* vote_b  = (const float*)d_in[4];
    const float* proj_w  = (const float*)d_in[5];
    const float* proj_b  = (const float*)d_in[6];
    float* out = (float*)d_out;

    hough_row_kernel<<<NB * NN, 256>>>(queries, cur_ref, vote_w, vote_b);

    dim3 gridB((NN2 / 4 + 255) / 256, NB);
    embed_proj_kernel<<<gridB, 256>>>(proj_w, proj_b, out);
}

// round 4
// speedup vs baseline: 1.5128x; 1.0355x over previous
#include <cuda_runtime.h>

#define NB 4
#define NN 900
#define ND 256
#define NV 16
#define NH 8
#define NN2 (NN * NN)

// scratch: x = 1 - imap/Z, laid out (B,N,N) contiguous
__device__ float g_x[NB * NN2];

__device__ __forceinline__ float fast_ex2(float x) {
    float r; asm("ex2.approx.ftz.f32 %0, %1;" : "=f"(r) : "f"(x)); return r;
}
__device__ __forceinline__ float fast_sin(float x) {
    float r; asm("sin.approx.ftz.f32 %0, %1;" : "=f"(r) : "f"(x)); return r;
}
__device__ __forceinline__ float fast_cos(float x) {
    float r; asm("cos.approx.ftz.f32 %0, %1;" : "=f"(r) : "f"(x)); return r;
}
__device__ __forceinline__ unsigned long long pack2(float a, float b) {
    unsigned long long r;
    asm("mov.b64 %0, {%1, %2};" : "=l"(r)
        : "r"(__float_as_uint(a)), "r"(__float_as_uint(b)));
    return r;
}
__device__ __forceinline__ float2 unpack2(unsigned long long v) {
    unsigned int lo, hi;
    asm("mov.b64 {%0, %1}, %2;" : "=r"(lo), "=r"(hi) : "l"(v));
    return make_float2(__uint_as_float(lo), __uint_as_float(hi));
}
__device__ __forceinline__ unsigned long long fma2(unsigned long long a,
                                                   unsigned long long b,
                                                   unsigned long long c) {
    unsigned long long d;
    asm("fma.rn.f32x2 %0, %1, %2, %3;" : "=l"(d) : "l"(a), "l"(b), "l"(c));
    return d;
}

// ---------------------------------------------------------------------------
// Kernel A: one block per (b,n) row. 4 vote-groups of 64 threads; each group
// handles 4 votes with registerized coefficients (16 regs).
// e = ninv*d2 folded: e = Ni*cc + C0 + Ax*cx + Ay*cy, arg = min(e, 0).
// ---------------------------------------------------------------------------
__global__ __launch_bounds__(256, 4)
void hough_row_kernel(const float* __restrict__ q,     // (B,N,D)
                      const float* __restrict__ cur,   // (B,N,4)
                      const float* __restrict__ vw,    // (32,D)
                      const float* __restrict__ vb)    // (32)
{
    const int bn   = blockIdx.x;
    const int b    = bn / NN;
    const int n    = bn % NN;
    const int tid  = threadIdx.x;
    const int lane = tid & 31;
    const int w    = tid >> 5;
    const int g    = tid >> 6;          // vote group 0..3 (votes g*4..g*4+3)
    const int tg   = tid & 63;          // thread index within group

    __shared__ float  sq[ND];
    __shared__ float2 sC[NN];
    __shared__ float  sI[4][NN];
    __shared__ float4 sCoef[NV];        // (Ax, Ay, Ni, C0)
    __shared__ float  sVotes[2 * NV];
    __shared__ float  sRed[8];
    __shared__ float  sInvZ;

    sq[tid] = q[bn * ND + tid];
    for (int j = tid; j < NN; j += 256) {
        float4 c4 = *reinterpret_cast<const float4*>(cur + (b * NN + j) * 4);
        sC[j] = make_float2(c4.x, c4.y);
    }
    __syncthreads();

    // votes = q_row @ vote_w.T + vote_b  (8 warps x 4 outputs)
    {
        const int k0 = w * 4;
        const float* w0 = vw + (k0 + 0) * ND;
        const float* w1 = vw + (k0 + 1) * ND;
        const float* w2 = vw + (k0 + 2) * ND;
        const float* w3 = vw + (k0 + 3) * ND;
        float a0 = 0.f, a1 = 0.f, a2 = 0.f, a3 = 0.f;
        #pragma unroll
        for (int i = 0; i < 8; i++) {
            int d = lane + 32 * i;
            float qv = sq[d];
            a0 = fmaf(qv, __ldg(w0 + d), a0);
            a1 = fmaf(qv, __ldg(w1 + d), a1);
            a2 = fmaf(qv, __ldg(w2 + d), a2);
            a3 = fmaf(qv, __ldg(w3 + d), a3);
        }
        #pragma unroll
        for (int o = 16; o; o >>= 1) {
            a0 += __shfl_down_sync(0xffffffffu, a0, o);
            a1 += __shfl_down_sync(0xffffffffu, a1, o);
            a2 += __shfl_down_sync(0xffffffffu, a2, o);
            a3 += __shfl_down_sync(0xffffffffu, a3, o);
        }
        if (lane == 0) {
            sVotes[k0 + 0] = a0 + vb[k0 + 0];
            sVotes[k0 + 1] = a1 + vb[k0 + 1];
            sVotes[k0 + 2] = a2 + vb[k0 + 2];
            sVotes[k0 + 3] = a3 + vb[k0 + 3];
        }
    }
    __syncthreads();

    if (tid < NV) {
        float cx = cur[bn * 4 + 0];
        float cy = cur[bn * 4 + 1];
        float vx = cx + sVotes[2 * tid + 0];
        float vy = cy + sVotes[2 * tid + 1];
        // reference quirk: sigma index is (n*V + v) mod N
        int idx  = (n * NV + tid) % NN;
        float c2 = cur[(b * NN + idx) * 4 + 2];
        float c3 = cur[(b * NN + idx) * 4 + 3];
        float s  = c2 + c3;   // 4*sigma
        // exp(-d2/(2 sigma^2)) = 2^(d2 * ninv), ninv = -8*log2e / s^2
        float ninv = -11.541560327111707f / (s * s);
        float vv   = fmaf(vx, vx, vy * vy);
        sCoef[tid] = make_float4(-2.f * ninv * vx,   // Ax
                                 -2.f * ninv * vy,   // Ay
                                 ninv,               // Ni
                                 ninv * vv);         // C0
    }
    __syncthreads();

    // registerize this group's 4 coefficient quads
    float Ax[4], Ay[4], Ni[4], C0[4];
    #pragma unroll
    for (int v = 0; v < 4; v++) {
        float4 c = sCoef[g * 4 + v];
        Ax[v] = c.x; Ay[v] = c.y; Ni[v] = c.z; C0[v] = c.w;
    }

    float part = 0.f;
    for (int m = tg; m < NN; m += 64) {
        float2 c  = sC[m];
        float  cc = fmaf(c.x, c.x, c.y * c.y);
        float acc = 0.f;
        #pragma unroll
        for (int v = 0; v < 4; v++) {
            float e = fmaf(c.x, Ax[v], fmaf(c.y, Ay[v], fmaf(cc, Ni[v], C0[v])));
            acc += fast_ex2(fminf(e, 0.f));
        }
        sI[g][m] = acc;
        part += acc;
    }
    #pragma unroll
    for (int o = 16; o; o >>= 1) part += __shfl_down_sync(0xffffffffu, part, o);
    if (lane == 0) sRed[w] = part;
    __syncthreads();
    if (tid == 0) {
        float t = 0.f;
        #pragma unroll
        for (int i = 0; i < 8; i++) t += sRed[i];
        sInvZ = 1.f / fmaxf(t, 1e-12f);
    }
    __syncthreads();
    const float invZ = sInvZ;

    float* xr = g_x + (size_t)bn * NN;
    for (int m = tid; m < NN; m += 256) {
        float s = (sI[0][m] + sI[1][m]) + (sI[2][m] + sI[3][m]);
        xr[m] = 1.f - s * invZ;
    }
}

// ---------------------------------------------------------------------------
// Kernel B: 2 consecutive elements per thread packed into f32x2 lanes.
// Heads processed in pairs for 2-way FMA2 ILP. blockIdx.y = batch.
// ---------------------------------------------------------------------------
__global__ __launch_bounds__(256, 4)
void embed_proj_kernel(const float* __restrict__ pw,   // (H,16)
                       const float* __restrict__ pb,   // (H)
                       float* __restrict__ out)        // (B,H,N,N)
{
    __shared__ unsigned long long sWb[NH][16];  // (w,w) duplicated
    __shared__ unsigned long long sBb[NH];      // (b,b) duplicated

    const int tid = threadIdx.x;
    if (tid < NH * 16) {
        int p = tid >> 4, k = tid & 15;
        float wv = pw[p * 16 + k];
        sWb[p][k] = pack2(wv, wv);
    }
    if (tid < NH) sBb[tid] = pack2(pb[tid], pb[tid]);
    __syncthreads();

    const int b  = blockIdx.y;
    const int r2 = (blockIdx.x * 256 + tid) * 2;
    if (r2 >= NN2) return;

    const float2 xv = *reinterpret_cast<const float2*>(g_x + (size_t)b * NN2 + r2);

    // 100 / 10000^(j/8)
    const float SCJ[8] = {100.f, 31.622776601683793f, 10.f, 3.1622776601683795f,
                          1.f, 0.31622776601683794f, 0.1f, 0.031622776601683794f};

    // f[k]: features for the element pair, k even=sin_j, odd=cos_j
    unsigned long long f[16];
    #pragma unroll
    for (int j = 0; j < 8; j++) {
        float t0 = xv.x * SCJ[j];
        float t1 = xv.y * SCJ[j];
        f[2 * j + 0] = pack2(fast_sin(t0), fast_sin(t1));
        f[2 * j + 1] = pack2(fast_cos(t0), fast_cos(t1));
    }

    float* obase = out + ((size_t)b * NH) * NN2 + r2;
    #pragma unroll
    for (int hp = 0; hp < 4; hp++) {
        unsigned long long a0 = sBb[2 * hp + 0];
        unsigned long long a1 = sBb[2 * hp + 1];
        #pragma unroll
        for (int k = 0; k < 16; k++) {
            unsigned long long fk = f[k];
            a0 = fma2(fk, sWb[2 * hp + 0][k], a0);
            a1 = fma2(fk, sWb[2 * hp + 1][k], a1);
        }
        float2 o0 = unpack2(a0);
        float2 o1 = unpack2(a1);
        *reinterpret_cast<float2*>(obase + (size_t)(2 * hp + 0) * NN2) =
            make_float2(fmaxf(o0.x, 0.f), fmaxf(o0.y, 0.f));
        *reinterpret_cast<float2*>(obase + (size_t)(2 * hp + 1) * NN2) =
            make_float2(fmaxf(o1.x, 0.f), fmaxf(o1.y, 0.f));
    }
}

extern "C" void kernel_launch(void* const* d_in, const int* in_sizes, int n_in,
                              void* d_out, int out_size) {
    const float* queries = (const float*)d_in[0];
    const float* cur_ref = (const float*)d_in[1];
    // d_in[2] = prev_ref_points — unused by the reference
    const float* vote_w  = (const float*)d_in[3];
    const float* vote_b  = (const float*)d_in[4];
    const float* proj_w  = (const float*)d_in[5];
    const float* proj_b  = (const float*)d_in[6];
    float* out = (float*)d_out;

    hough_row_kernel<<<NB * NN, 256>>>(queries, cur_ref, vote_w, vote_b);

    dim3 gridB((NN2 / 2 + 255) / 256, NB);
    embed_proj_kernel<<<gridB, 256>>>(proj_w, proj_b, out);
}

// round 5
// speedup vs baseline: 1.5227x; 1.0065x over previous
#include <cuda_runtime.h>

#define NB 4
#define NN 900
#define ND 256
#define NV 16
#define NH 8
#define NN2 (NN * NN)

// scratch: x = 1 - imap/Z, laid out (B,N,N) contiguous
__device__ float g_x[NB * NN2];

__device__ __forceinline__ float fast_ex2(float x) {
    float r; asm("ex2.approx.ftz.f32 %0, %1;" : "=f"(r) : "f"(x)); return r;
}
__device__ __forceinline__ float fast_sin(float x) {
    float r; asm("sin.approx.ftz.f32 %0, %1;" : "=f"(r) : "f"(x)); return r;
}
__device__ __forceinline__ float fast_cos(float x) {
    float r; asm("cos.approx.ftz.f32 %0, %1;" : "=f"(r) : "f"(x)); return r;
}
__device__ __forceinline__ unsigned long long pack2(float a, float b) {
    unsigned long long r;
    asm("mov.b64 %0, {%1, %2};" : "=l"(r)
        : "r"(__float_as_uint(a)), "r"(__float_as_uint(b)));
    return r;
}
__device__ __forceinline__ float2 unpack2(unsigned long long v) {
    unsigned int lo, hi;
    asm("mov.b64 {%0, %1}, %2;" : "=r"(lo), "=r"(hi) : "l"(v));
    return make_float2(__uint_as_float(lo), __uint_as_float(hi));
}
__device__ __forceinline__ unsigned long long fma2(unsigned long long a,
                                                   unsigned long long b,
                                                   unsigned long long c) {
    unsigned long long d;
    asm("fma.rn.f32x2 %0, %1, %2, %3;" : "=l"(d) : "l"(a), "l"(b), "l"(c));
    return d;
}

// ---------------------------------------------------------------------------
// Kernel A: one block per (b,n) row. 4 vote-groups of 64 threads; each group
// handles 4 votes with registerized coefficients (16 regs).
// e = ninv*d2 folded: e = Ni*cc + C0 + Ax*cx + Ay*cy, arg = min(e, 0).
// ---------------------------------------------------------------------------
__global__ __launch_bounds__(256, 5)
void hough_row_kernel(const float* __restrict__ q,     // (B,N,D)
                      const float* __restrict__ cur,   // (B,N,4)
                      const float* __restrict__ vw,    // (32,D)
                      const float* __restrict__ vb)    // (32)
{
    const int bn   = blockIdx.x;
    const int b    = bn / NN;
    const int n    = bn % NN;
    const int tid  = threadIdx.x;
    const int lane = tid & 31;
    const int w    = tid >> 5;
    const int g    = tid >> 6;          // vote group 0..3 (votes g*4..g*4+3)
    const int tg   = tid & 63;          // thread index within group

    __shared__ float  sq[ND];
    __shared__ float2 sC[NN];
    __shared__ float  sI[4][NN];
    __shared__ float4 sCoef[NV];        // (Ax, Ay, Ni, C0)
    __shared__ float  sVotes[2 * NV];
    __shared__ float  sRed[8];
    __shared__ float  sInvZ;

    sq[tid] = q[bn * ND + tid];
    for (int j = tid; j < NN; j += 256) {
        float4 c4 = *reinterpret_cast<const float4*>(cur + (b * NN + j) * 4);
        sC[j] = make_float2(c4.x, c4.y);
    }
    __syncthreads();

    // votes = q_row @ vote_w.T + vote_b  (8 warps x 4 outputs)
    {
        const int k0 = w * 4;
        const float* w0 = vw + (k0 + 0) * ND;
        const float* w1 = vw + (k0 + 1) * ND;
        const float* w2 = vw + (k0 + 2) * ND;
        const float* w3 = vw + (k0 + 3) * ND;
        float a0 = 0.f, a1 = 0.f, a2 = 0.f, a3 = 0.f;
        #pragma unroll
        for (int i = 0; i < 8; i++) {
            int d = lane + 32 * i;
            float qv = sq[d];
            a0 = fmaf(qv, __ldg(w0 + d), a0);
            a1 = fmaf(qv, __ldg(w1 + d), a1);
            a2 = fmaf(qv, __ldg(w2 + d), a2);
            a3 = fmaf(qv, __ldg(w3 + d), a3);
        }
        #pragma unroll
        for (int o = 16; o; o >>= 1) {
            a0 += __shfl_down_sync(0xffffffffu, a0, o);
            a1 += __shfl_down_sync(0xffffffffu, a1, o);
            a2 += __shfl_down_sync(0xffffffffu, a2, o);
            a3 += __shfl_down_sync(0xffffffffu, a3, o);
        }
        if (lane == 0) {
            sVotes[k0 + 0] = a0 + vb[k0 + 0];
            sVotes[k0 + 1] = a1 + vb[k0 + 1];
            sVotes[k0 + 2] = a2 + vb[k0 + 2];
            sVotes[k0 + 3] = a3 + vb[k0 + 3];
        }
    }
    __syncthreads();

    if (tid < NV) {
        float cx = cur[bn * 4 + 0];
        float cy = cur[bn * 4 + 1];
        float vx = cx + sVotes[2 * tid + 0];
        float vy = cy + sVotes[2 * tid + 1];
        // reference quirk: sigma index is (n*V + v) mod N
        int idx  = (n * NV + tid) % NN;
        float c2 = cur[(b * NN + idx) * 4 + 2];
        float c3 = cur[(b * NN + idx) * 4 + 3];
        float s  = c2 + c3;   // 4*sigma
        // exp(-d2/(2 sigma^2)) = 2^(d2 * ninv), ninv = -8*log2e / s^2
        float ninv = -11.541560327111707f / (s * s);
        float vv   = fmaf(vx, vx, vy * vy);
        sCoef[tid] = make_float4(-2.f * ninv * vx,   // Ax
                                 -2.f * ninv * vy,   // Ay
                                 ninv,               // Ni
                                 ninv * vv);         // C0
    }
    __syncthreads();

    // registerize this group's 4 coefficient quads
    float Ax[4], Ay[4], Ni[4], C0[4];
    #pragma unroll
    for (int v = 0; v < 4; v++) {
        float4 c = sCoef[g * 4 + v];
        Ax[v] = c.x; Ay[v] = c.y; Ni[v] = c.z; C0[v] = c.w;
    }

    float part = 0.f;
    for (int m = tg; m < NN; m += 64) {
        float2 c  = sC[m];
        float  cc = fmaf(c.x, c.x, c.y * c.y);
        float e0 = fast_ex2(fminf(fmaf(c.x, Ax[0], fmaf(c.y, Ay[0], fmaf(cc, Ni[0], C0[0]))), 0.f));
        float e1 = fast_ex2(fminf(fmaf(c.x, Ax[1], fmaf(c.y, Ay[1], fmaf(cc, Ni[1], C0[1]))), 0.f));
        float e2 = fast_ex2(fminf(fmaf(c.x, Ax[2], fmaf(c.y, Ay[2], fmaf(cc, Ni[2], C0[2]))), 0.f));
        float e3 = fast_ex2(fminf(fmaf(c.x, Ax[3], fmaf(c.y, Ay[3], fmaf(cc, Ni[3], C0[3]))), 0.f));
        float acc = (e0 + e1) + (e2 + e3);
        sI[g][m] = acc;
        part += acc;
    }
    #pragma unroll
    for (int o = 16; o; o >>= 1) part += __shfl_down_sync(0xffffffffu, part, o);
    if (lane == 0) sRed[w] = part;
    __syncthreads();
    if (tid == 0) {
        float t = 0.f;
        #pragma unroll
        for (int i = 0; i < 8; i++) t += sRed[i];
        sInvZ = 1.f / fmaxf(t, 1e-12f);
    }
    __syncthreads();
    const float invZ = sInvZ;

    float* xr = g_x + (size_t)bn * NN;
    for (int m = tid; m < NN; m += 256) {
        float s = (sI[0][m] + sI[1][m]) + (sI[2][m] + sI[3][m]);
        xr[m] = 1.f - s * invZ;
    }
}

// ---------------------------------------------------------------------------
// Kernel B: 2 consecutive elements per thread packed into f32x2 lanes.
// Weights in shared as ulonglong2 {(ws,ws),(wc,wc)} -> one LDS.128 feeds
// two fma2. Heads processed in pairs for ILP. blockIdx.y = batch.
// ---------------------------------------------------------------------------
__global__ __launch_bounds__(256, 4)
void embed_proj_kernel(const float* __restrict__ pw,   // (H,16)
                       const float* __restrict__ pb,   // (H)
                       float* __restrict__ out)        // (B,H,N,N)
{
    __shared__ ulonglong2 sW[NH][8];            // {(ws,ws),(wc,wc)} per (h,j)
    __shared__ unsigned long long sBb[NH];      // (b,b) duplicated

    const int tid = threadIdx.x;
    if (tid < NH * 8) {
        int h = tid >> 3, j = tid & 7;
        float ws = pw[h * 16 + 2 * j + 0];
        float wc = pw[h * 16 + 2 * j + 1];
        ulonglong2 v;
        v.x = pack2(ws, ws);
        v.y = pack2(wc, wc);
        sW[h][j] = v;
    }
    if (tid < NH) sBb[tid] = pack2(pb[tid], pb[tid]);
    __syncthreads();

    const int b  = blockIdx.y;
    const int r2 = (blockIdx.x * 256 + tid) * 2;
    if (r2 >= NN2) return;

    const float2 xv = *reinterpret_cast<const float2*>(g_x + (size_t)b * NN2 + r2);

    // 100 / 10000^(j/8)
    const float SCJ[8] = {100.f, 31.622776601683793f, 10.f, 3.1622776601683795f,
                          1.f, 0.31622776601683794f, 0.1f, 0.031622776601683794f};

    // fs[j] = (sin_j(e0), sin_j(e1)), fc[j] = (cos_j(e0), cos_j(e1))
    unsigned long long fs[8], fc[8];
    #pragma unroll
    for (int j = 0; j < 8; j++) {
        float t0 = xv.x * SCJ[j];
        float t1 = xv.y * SCJ[j];
        fs[j] = pack2(fast_sin(t0), fast_sin(t1));
        fc[j] = pack2(fast_cos(t0), fast_cos(t1));
    }

    float* obase = out + ((size_t)b * NH) * NN2 + r2;
    #pragma unroll
    for (int hp = 0; hp < 4; hp++) {
        const int h0 = 2 * hp, h1 = 2 * hp + 1;
        unsigned long long a0 = sBb[h0];
        unsigned long long a1 = sBb[h1];
        #pragma unroll
        for (int j = 0; j < 8; j++) {
            ulonglong2 w0 = sW[h0][j];     // LDS.128
            ulonglong2 w1 = sW[h1][j];     // LDS.128
            a0 = fma2(fs[j], w0.x, a0);
            a0 = fma2(fc[j], w0.y, a0);
            a1 = fma2(fs[j], w1.x, a1);
            a1 = fma2(fc[j], w1.y, a1);
        }
        float2 o0 = unpack2(a0);
        float2 o1 = unpack2(a1);
        *reinterpret_cast<float2*>(obase + (size_t)h0 * NN2) =
            make_float2(fmaxf(o0.x, 0.f), fmaxf(o0.y, 0.f));
        *reinterpret_cast<float2*>(obase + (size_t)h1 * NN2) =
            make_float2(fmaxf(o1.x, 0.f), fmaxf(o1.y, 0.f));
    }
}

extern "C" void kernel_launch(void* const* d_in, const int* in_sizes, int n_in,
                              void* d_out, int out_size) {
    const float* queries = (const float*)d_in[0];
    const float* cur_ref = (const float*)d_in[1];
    // d_in[2] = prev_ref_points — unused by the reference
    const float* vote_w  = (const float*)d_in[3];
    const float* vote_b  = (const float*)d_in[4];
    const float* proj_w  = (const float*)d_in[5];
    const float* proj_b  = (const float*)d_in[6];
    float* out = (float*)d_out;

    hough_row_kernel<<<NB * NN, 256>>>(queries, cur_ref, vote_w, vote_b);

    dim3 gridB((NN2 / 2 + 255) / 256, NB);
    embed_proj_kernel<<<gridB, 256>>>(proj_w, proj_b, out);
}

// round 6
// speedup vs baseline: 1.5725x; 1.0328x over previous
#include <cuda_runtime.h>

#define NB 4
#define NN 900
#define ND 256
#define NV 16
#define NH 8
#define NN2 (NN * NN)

// scratch: x = 1 - imap/Z, laid out (B,N,N) contiguous
__device__ float g_x[NB * NN2];

__device__ __forceinline__ float fast_ex2(float x) {
    float r; asm("ex2.approx.ftz.f32 %0, %1;" : "=f"(r) : "f"(x)); return r;
}
__device__ __forceinline__ float fast_sin(float x) {
    float r; asm("sin.approx.ftz.f32 %0, %1;" : "=f"(r) : "f"(x)); return r;
}
__device__ __forceinline__ float fast_cos(float x) {
    float r; asm("cos.approx.ftz.f32 %0, %1;" : "=f"(r) : "f"(x)); return r;
}
__device__ __forceinline__ unsigned long long pack2(float a, float b) {
    unsigned long long r;
    asm("mov.b64 %0, {%1, %2};" : "=l"(r)
        : "r"(__float_as_uint(a)), "r"(__float_as_uint(b)));
    return r;
}
__device__ __forceinline__ float2 unpack2(unsigned long long v) {
    unsigned int lo, hi;
    asm("mov.b64 {%0, %1}, %2;" : "=r"(lo), "=r"(hi) : "l"(v));
    return make_float2(__uint_as_float(lo), __uint_as_float(hi));
}
__device__ __forceinline__ unsigned long long fma2(unsigned long long a,
                                                   unsigned long long b,
                                                   unsigned long long c) {
    unsigned long long d;
    asm("fma.rn.f32x2 %0, %1, %2, %3;" : "=l"(d) : "l"(a), "l"(b), "l"(c));
    return d;
}

// ---------------------------------------------------------------------------
// Kernel A: one block per (b,n) row. 4 vote-groups of 64 threads; each group
// handles 4 votes with registerized coefficients.
// e = ninv*d2 folded: e = Ni*cc + C0 + Ax*cx + Ay*cy, arg = min(e, 0).
// ---------------------------------------------------------------------------
__global__ __launch_bounds__(256, 5)
void hough_row_kernel(const float* __restrict__ q,     // (B,N,D)
                      const float* __restrict__ cur,   // (B,N,4)
                      const float* __restrict__ vw,    // (32,D)
                      const float* __restrict__ vb)    // (32)
{
    const int bn   = blockIdx.x;
    const int b    = bn / NN;
    const int n    = bn % NN;
    const int tid  = threadIdx.x;
    const int lane = tid & 31;
    const int w    = tid >> 5;
    const int g    = tid >> 6;          // vote group 0..3 (votes g*4..g*4+3)
    const int tg   = tid & 63;          // thread index within group

    __shared__ float4 sq4[ND / 4];      // query row as float4
    __shared__ float2 sC[NN];
    __shared__ float  sI[4][NN];
    __shared__ float4 sCoef[NV];        // (Ax, Ay, Ni, C0)
    __shared__ float  sVotes[2 * NV];
    __shared__ float  sRed[8];
    __shared__ float  sInvZ;

    if (tid < ND / 4)
        sq4[tid] = *reinterpret_cast<const float4*>(q + bn * ND + tid * 4);
    for (int j = tid; j < NN; j += 256) {
        float4 c4 = *reinterpret_cast<const float4*>(cur + (b * NN + j) * 4);
        sC[j] = make_float2(c4.x, c4.y);
    }
    __syncthreads();

    // votes = q_row @ vote_w.T + vote_b  (8 warps x 4 outputs, float4 loads)
    {
        const int k0 = w * 4;
        const float4* w0 = reinterpret_cast<const float4*>(vw + (k0 + 0) * ND);
        const float4* w1 = reinterpret_cast<const float4*>(vw + (k0 + 1) * ND);
        const float4* w2 = reinterpret_cast<const float4*>(vw + (k0 + 2) * ND);
        const float4* w3 = reinterpret_cast<const float4*>(vw + (k0 + 3) * ND);
        float a0 = 0.f, a1 = 0.f, a2 = 0.f, a3 = 0.f;
        #pragma unroll
        for (int i = 0; i < 2; i++) {
            int d = lane + 32 * i;
            float4 qv = sq4[d];
            float4 v0 = __ldg(w0 + d);
            float4 v1 = __ldg(w1 + d);
            float4 v2 = __ldg(w2 + d);
            float4 v3 = __ldg(w3 + d);
            a0 = fmaf(qv.x, v0.x, fmaf(qv.y, v0.y, fmaf(qv.z, v0.z, fmaf(qv.w, v0.w, a0))));
            a1 = fmaf(qv.x, v1.x, fmaf(qv.y, v1.y, fmaf(qv.z, v1.z, fmaf(qv.w, v1.w, a1))));
            a2 = fmaf(qv.x, v2.x, fmaf(qv.y, v2.y, fmaf(qv.z, v2.z, fmaf(qv.w, v2.w, a2))));
            a3 = fmaf(qv.x, v3.x, fmaf(qv.y, v3.y, fmaf(qv.z, v3.z, fmaf(qv.w, v3.w, a3))));
        }
        #pragma unroll
        for (int o = 16; o; o >>= 1) {
            a0 += __shfl_down_sync(0xffffffffu, a0, o);
            a1 += __shfl_down_sync(0xffffffffu, a1, o);
            a2 += __shfl_down_sync(0xffffffffu, a2, o);
            a3 += __shfl_down_sync(0xffffffffu, a3, o);
        }
        if (lane == 0) {
            sVotes[k0 + 0] = a0 + vb[k0 + 0];
            sVotes[k0 + 1] = a1 + vb[k0 + 1];
            sVotes[k0 + 2] = a2 + vb[k0 + 2];
            sVotes[k0 + 3] = a3 + vb[k0 + 3];
        }
    }
    __syncthreads();

    if (tid < NV) {
        float cx = cur[bn * 4 + 0];
        float cy = cur[bn * 4 + 1];
        float vx = cx + sVotes[2 * tid + 0];
        float vy = cy + sVotes[2 * tid + 1];
        // reference quirk: sigma index is (n*V + v) mod N
        int idx  = (n * NV + tid) % NN;
        float c2 = cur[(b * NN + idx) * 4 + 2];
        float c3 = cur[(b * NN + idx) * 4 + 3];
        float s  = c2 + c3;   // 4*sigma
        // exp(-d2/(2 sigma^2)) = 2^(d2 * ninv), ninv = -8*log2e / s^2
        float ninv = -11.541560327111707f / (s * s);
        float vv   = fmaf(vx, vx, vy * vy);
        sCoef[tid] = make_float4(-2.f * ninv * vx, -2.f * ninv * vy,
                                 ninv, ninv * vv);
    }
    __syncthreads();

    float Ax[4], Ay[4], Ni[4], C0[4];
    #pragma unroll
    for (int v = 0; v < 4; v++) {
        float4 c = sCoef[g * 4 + v];
        Ax[v] = c.x; Ay[v] = c.y; Ni[v] = c.z; C0[v] = c.w;
    }

    float part = 0.f;
    for (int m = tg; m < NN; m += 64) {
        float2 c  = sC[m];
        float  cc = fmaf(c.x, c.x, c.y * c.y);
        float e0 = fast_ex2(fminf(fmaf(c.x, Ax[0], fmaf(c.y, Ay[0], fmaf(cc, Ni[0], C0[0]))), 0.f));
        float e1 = fast_ex2(fminf(fmaf(c.x, Ax[1], fmaf(c.y, Ay[1], fmaf(cc, Ni[1], C0[1]))), 0.f));
        float e2 = fast_ex2(fminf(fmaf(c.x, Ax[2], fmaf(c.y, Ay[2], fmaf(cc, Ni[2], C0[2]))), 0.f));
        float e3 = fast_ex2(fminf(fmaf(c.x, Ax[3], fmaf(c.y, Ay[3], fmaf(cc, Ni[3], C0[3]))), 0.f));
        float acc = (e0 + e1) + (e2 + e3);
        sI[g][m] = acc;
        part += acc;
    }
    #pragma unroll
    for (int o = 16; o; o >>= 1) part += __shfl_down_sync(0xffffffffu, part, o);
    if (lane == 0) sRed[w] = part;
    __syncthreads();
    if (tid == 0) {
        float t = 0.f;
        #pragma unroll
        for (int i = 0; i < 8; i++) t += sRed[i];
        sInvZ = 1.f / fmaxf(t, 1e-12f);
    }
    __syncthreads();
    const float invZ = sInvZ;

    float* xr = g_x + (size_t)bn * NN;
    for (int m = tid; m < NN; m += 256) {
        float s = (sI[0][m] + sI[1][m]) + (sI[2][m] + sI[3][m]);
        xr[m] = 1.f - s * invZ;
    }
}

// ---------------------------------------------------------------------------
// Kernel B: 8 elements per thread (4 f32x2 pairs), j-outer loop, all 8 head
// accumulators in registers. Weights loaded once per (j,h) and reused across
// 4 element-pairs -> 128 B of weight LDS per element (was 512).
// ---------------------------------------------------------------------------
__global__ __launch_bounds__(256, 2)
void embed_proj_kernel(const float* __restrict__ pw,   // (H,16)
                       const float* __restrict__ pb,   // (H)
                       float* __restrict__ out)        // (B,H,N,N)
{
    __shared__ ulonglong2 sW[8][NH];            // [j][h] = {(ws,ws),(wc,wc)}
    __shared__ unsigned long long sBb[NH];      // (b,b)

    const int tid = threadIdx.x;
    if (tid < 8 * NH) {
        int j = tid >> 3, h = tid & 7;
        float ws = pw[h * 16 + 2 * j + 0];
        float wc = pw[h * 16 + 2 * j + 1];
        ulonglong2 v; v.x = pack2(ws, ws); v.y = pack2(wc, wc);
        sW[j][h] = v;
    }
    if (tid < NH) sBb[tid] = pack2(pb[tid], pb[tid]);
    __syncthreads();

    const int b = blockIdx.y;
    const int r8 = (blockIdx.x * 256 + tid) * 8;
    if (r8 >= NN2) return;   // NN2 % 8 == 0, so full 8-vectors only

    const float4* xp = reinterpret_cast<const float4*>(g_x + (size_t)b * NN2 + r8);
    float4 xa = xp[0], xb = xp[1];
    const float xs[8] = {xa.x, xa.y, xa.z, xa.w, xb.x, xb.y, xb.z, xb.w};

    unsigned long long acc[NH][4];
    #pragma unroll
    for (int h = 0; h < NH; h++) {
        unsigned long long bb = sBb[h];
        #pragma unroll
        for (int p = 0; p < 4; p++) acc[h][p] = bb;
    }

    // 100 / 10000^(j/8)
    const float SCJ[8] = {100.f, 31.622776601683793f, 10.f, 3.1622776601683795f,
                          1.f, 0.31622776601683794f, 0.1f, 0.031622776601683794f};

    #pragma unroll
    for (int j = 0; j < 8; j++) {
        unsigned long long fs[4], fc[4];
        #pragma unroll
        for (int p = 0; p < 4; p++) {
            float t0 = xs[2 * p + 0] * SCJ[j];
            float t1 = xs[2 * p + 1] * SCJ[j];
            fs[p] = pack2(fast_sin(t0), fast_sin(t1));
            fc[p] = pack2(fast_cos(t0), fast_cos(t1));
        }
        #pragma unroll
        for (int h = 0; h < NH; h++) {
            ulonglong2 w = sW[j][h];        // one LDS.128 feeds 8 fma2
            #pragma unroll
            for (int p = 0; p < 4; p++) {
                acc[h][p] = fma2(fs[p], w.x, acc[h][p]);
                acc[h][p] = fma2(fc[p], w.y, acc[h][p]);
            }
        }
    }

    float* ob = out + ((size_t)b * NH) * NN2 + r8;
    #pragma unroll
    for (int h = 0; h < NH; h++) {
        float2 o0 = unpack2(acc[h][0]);
        float2 o1 = unpack2(acc[h][1]);
        float2 o2 = unpack2(acc[h][2]);
        float2 o3 = unpack2(acc[h][3]);
        float4 v0 = make_float4(fmaxf(o0.x, 0.f), fmaxf(o0.y, 0.f),
                                fmaxf(o1.x, 0.f), fmaxf(o1.y, 0.f));
        float4 v1 = make_float4(fmaxf(o2.x, 0.f), fmaxf(o2.y, 0.f),
                                fmaxf(o3.x, 0.f), fmaxf(o3.y, 0.f));
        float4* dst = reinterpret_cast<float4*>(ob + (size_t)h * NN2);
        dst[0] = v0;
        dst[1] = v1;
    }
}

extern "C" void kernel_launch(void* const* d_in, const int* in_sizes, int n_in,
                              void* d_out, int out_size) {
    const float* queries = (const float*)d_in[0];
    const float* cur_ref = (const float*)d_in[1];
    // d_in[2] = prev_ref_points — unused by the reference
    const float* vote_w  = (const float*)d_in[3];
    const float* vote_b  = (const float*)d_in[4];
    const float* proj_w  = (const float*)d_in[5];
    const float* proj_b  = (const float*)d_in[6];
    float* out = (float*)d_out;

    hough_row_kernel<<<NB * NN, 256>>>(queries, cur_ref, vote_w, vote_b);

    dim3 gridB((NN2 / 8 + 255) / 256, NB);
    embed_proj_kernel<<<gridB, 256>>>(proj_w, proj_b, out);
}

// round 7
// speedup vs baseline: 1.8011x; 1.1453x over previous
#include <cuda_runtime.h>

#define NB 4
#define NN 900
#define ND 256
#define NV 16
#define NH 8
#define NN2 (NN * NN)

// scratch: x = 1 - imap/Z, laid out (B,N,N) contiguous
__device__ float g_x[NB * NN2];

__device__ __forceinline__ float fast_ex2(float x) {
    float r; asm("ex2.approx.ftz.f32 %0, %1;" : "=f"(r) : "f"(x)); return r;
}
__device__ __forceinline__ float fast_sin(float x) {
    float r; asm("sin.approx.ftz.f32 %0, %1;" : "=f"(r) : "f"(x)); return r;
}
__device__ __forceinline__ float fast_cos(float x) {
    float r; asm("cos.approx.ftz.f32 %0, %1;" : "=f"(r) : "f"(x)); return r;
}
__device__ __forceinline__ unsigned long long pack2(float a, float b) {
    unsigned long long r;
    asm("mov.b64 %0, {%1, %2};" : "=l"(r)
        : "r"(__float_as_uint(a)), "r"(__float_as_uint(b)));
    return r;
}
__device__ __forceinline__ float2 unpack2(unsigned long long v) {
    unsigned int lo, hi;
    asm("mov.b64 {%0, %1}, %2;" : "=r"(lo), "=r"(hi) : "l"(v));
    return make_float2(__uint_as_float(lo), __uint_as_float(hi));
}
__device__ __forceinline__ unsigned long long fma2(unsigned long long a,
                                                   unsigned long long b,
                                                   unsigned long long c) {
    unsigned long long d;
    asm("fma.rn.f32x2 %0, %1, %2, %3;" : "=l"(d) : "l"(a), "l"(b), "l"(c));
    return d;
}

// ---------------------------------------------------------------------------
// Kernel A: TWO rows (n0, n0+1) per block. Shared sC / barriers / GEMM weight
// loads amortized across both rows; cc reused for both rows' vote evals.
// 4 vote-groups of 64 threads; each group: 4 votes x 2 rows.
// ---------------------------------------------------------------------------
__global__ __launch_bounds__(256, 4)
void hough_row2_kernel(const float* __restrict__ q,     // (B,N,D)
                       const float* __restrict__ cur,   // (B,N,4)
                       const float* __restrict__ vw,    // (32,D)
                       const float* __restrict__ vb)    // (32)
{
    const int pair = blockIdx.x;          // 0 .. NB*NN/2-1
    const int b    = pair / (NN / 2);
    const int n0   = (pair % (NN / 2)) * 2;
    const int bn0  = b * NN + n0;
    const int tid  = threadIdx.x;
    const int lane = tid & 31;
    const int w    = tid >> 5;
    const int g    = tid >> 6;            // vote group 0..3
    const int tg   = tid & 63;

    __shared__ float4 sq4[2][ND / 4];
    __shared__ float2 sC[NN];
    __shared__ float  sI[2][4][NN];
    __shared__ float4 sCoef[2][NV];       // (Ax, Ay, Ni, C0)
    __shared__ float  sVotes[2][2 * NV];
    __shared__ float  sRed[2][8];
    __shared__ float  sInvZ[2];

    if (tid < 128) {
        int r = tid >> 6, i = tid & 63;
        sq4[r][i] = *reinterpret_cast<const float4*>(q + (bn0 + r) * ND + i * 4);
    }
    for (int j = tid; j < NN; j += 256) {
        float4 c4 = *reinterpret_cast<const float4*>(cur + (b * NN + j) * 4);
        sC[j] = make_float2(c4.x, c4.y);
    }
    __syncthreads();

    // votes for BOTH rows: weight vectors loaded once, used with both q rows
    {
        const int k0 = w * 4;
        const float4* w0 = reinterpret_cast<const float4*>(vw + (k0 + 0) * ND);
        const float4* w1 = reinterpret_cast<const float4*>(vw + (k0 + 1) * ND);
        const float4* w2 = reinterpret_cast<const float4*>(vw + (k0 + 2) * ND);
        const float4* w3 = reinterpret_cast<const float4*>(vw + (k0 + 3) * ND);
        float a0 = 0.f, a1 = 0.f, a2 = 0.f, a3 = 0.f;
        float b0 = 0.f, b1 = 0.f, b2 = 0.f, b3 = 0.f;
        #pragma unroll
        for (int i = 0; i < 2; i++) {
            int d = lane + 32 * i;
            float4 qa = sq4[0][d];
            float4 qb = sq4[1][d];
            float4 v0 = __ldg(w0 + d);
            float4 v1 = __ldg(w1 + d);
            float4 v2 = __ldg(w2 + d);
            float4 v3 = __ldg(w3 + d);
            a0 = fmaf(qa.x, v0.x, fmaf(qa.y, v0.y, fmaf(qa.z, v0.z, fmaf(qa.w, v0.w, a0))));
            a1 = fmaf(qa.x, v1.x, fmaf(qa.y, v1.y, fmaf(qa.z, v1.z, fmaf(qa.w, v1.w, a1))));
            a2 = fmaf(qa.x, v2.x, fmaf(qa.y, v2.y, fmaf(qa.z, v2.z, fmaf(qa.w, v2.w, a2))));
            a3 = fmaf(qa.x, v3.x, fmaf(qa.y, v3.y, fmaf(qa.z, v3.z, fmaf(qa.w, v3.w, a3))));
            b0 = fmaf(qb.x, v0.x, fmaf(qb.y, v0.y, fmaf(qb.z, v0.z, fmaf(qb.w, v0.w, b0))));
            b1 = fmaf(qb.x, v1.x, fmaf(qb.y, v1.y, fmaf(qb.z, v1.z, fmaf(qb.w, v1.w, b1))));
            b2 = fmaf(qb.x, v2.x, fmaf(qb.y, v2.y, fmaf(qb.z, v2.z, fmaf(qb.w, v2.w, b2))));
            b3 = fmaf(qb.x, v3.x, fmaf(qb.y, v3.y, fmaf(qb.z, v3.z, fmaf(qb.w, v3.w, b3))));
        }
        #pragma unroll
        for (int o = 16; o; o >>= 1) {
            a0 += __shfl_down_sync(0xffffffffu, a0, o);
            a1 += __shfl_down_sync(0xffffffffu, a1, o);
            a2 += __shfl_down_sync(0xffffffffu, a2, o);
            a3 += __shfl_down_sync(0xffffffffu, a3, o);
            b0 += __shfl_down_sync(0xffffffffu, b0, o);
            b1 += __shfl_down_sync(0xffffffffu, b1, o);
            b2 += __shfl_down_sync(0xffffffffu, b2, o);
            b3 += __shfl_down_sync(0xffffffffu, b3, o);
        }
        if (lane == 0) {
            sVotes[0][k0 + 0] = a0 + vb[k0 + 0];
            sVotes[0][k0 + 1] = a1 + vb[k0 + 1];
            sVotes[0][k0 + 2] = a2 + vb[k0 + 2];
            sVotes[0][k0 + 3] = a3 + vb[k0 + 3];
            sVotes[1][k0 + 0] = b0 + vb[k0 + 0];
            sVotes[1][k0 + 1] = b1 + vb[k0 + 1];
            sVotes[1][k0 + 2] = b2 + vb[k0 + 2];
            sVotes[1][k0 + 3] = b3 + vb[k0 + 3];
        }
    }
    __syncthreads();

    if (tid < 2 * NV) {
        int r = tid >> 4, v = tid & 15;
        int n = n0 + r, bn = bn0 + r;
        float cx = cur[bn * 4 + 0];
        float cy = cur[bn * 4 + 1];
        float vx = cx + sVotes[r][2 * v + 0];
        float vy = cy + sVotes[r][2 * v + 1];
        // reference quirk: sigma index is (n*V + v) mod N
        int idx  = (n * NV + v) % NN;
        float c2 = cur[(b * NN + idx) * 4 + 2];
        float c3 = cur[(b * NN + idx) * 4 + 3];
        float s  = c2 + c3;   // 4*sigma
        float ninv = -11.541560327111707f / (s * s);   // -8*log2e / s^2
        float vv   = fmaf(vx, vx, vy * vy);
        sCoef[r][v] = make_float4(-2.f * ninv * vx, -2.f * ninv * vy,
                                  ninv, ninv * vv);
    }
    __syncthreads();

    // registerize this group's 4 votes for both rows
    float Ax[2][4], Ay[2][4], Ni[2][4], C0[2][4];
    #pragma unroll
    for (int r = 0; r < 2; r++)
        #pragma unroll
        for (int v = 0; v < 4; v++) {
            float4 c = sCoef[r][g * 4 + v];
            Ax[r][v] = c.x; Ay[r][v] = c.y; Ni[r][v] = c.z; C0[r][v] = c.w;
        }

    float part0 = 0.f, part1 = 0.f;
    for (int m = tg; m < NN; m += 64) {
        float2 c  = sC[m];
        float  cc = fmaf(c.x, c.x, c.y * c.y);
        float acc0, acc1;
        {
            float e0 = fast_ex2(fminf(fmaf(c.x, Ax[0][0], fmaf(c.y, Ay[0][0], fmaf(cc, Ni[0][0], C0[0][0]))), 0.f));
            float e1 = fast_ex2(fminf(fmaf(c.x, Ax[0][1], fmaf(c.y, Ay[0][1], fmaf(cc, Ni[0][1], C0[0][1]))), 0.f));
            float e2 = fast_ex2(fminf(fmaf(c.x, Ax[0][2], fmaf(c.y, Ay[0][2], fmaf(cc, Ni[0][2], C0[0][2]))), 0.f));
            float e3 = fast_ex2(fminf(fmaf(c.x, Ax[0][3], fmaf(c.y, Ay[0][3], fmaf(cc, Ni[0][3], C0[0][3]))), 0.f));
            acc0 = (e0 + e1) + (e2 + e3);
        }
        {
            float e0 = fast_ex2(fminf(fmaf(c.x, Ax[1][0], fmaf(c.y, Ay[1][0], fmaf(cc, Ni[1][0], C0[1][0]))), 0.f));
            float e1 = fast_ex2(fminf(fmaf(c.x, Ax[1][1], fmaf(c.y, Ay[1][1], fmaf(cc, Ni[1][1], C0[1][1]))), 0.f));
            float e2 = fast_ex2(fminf(fmaf(c.x, Ax[1][2], fmaf(c.y, Ay[1][2], fmaf(cc, Ni[1][2], C0[1][2]))), 0.f));
            float e3 = fast_ex2(fminf(fmaf(c.x, Ax[1][3], fmaf(c.y, Ay[1][3], fmaf(cc, Ni[1][3], C0[1][3]))), 0.f));
            acc1 = (e0 + e1) + (e2 + e3);
        }
        sI[0][g][m] = acc0;
        sI[1][g][m] = acc1;
        part0 += acc0;
        part1 += acc1;
    }
    #pragma unroll
    for (int o = 16; o; o >>= 1) {
        part0 += __shfl_down_sync(0xffffffffu, part0, o);
        part1 += __shfl_down_sync(0xffffffffu, part1, o);
    }
    if (lane == 0) { sRed[0][w] = part0; sRed[1][w] = part1; }
    __syncthreads();
    if (tid < 2) {
        float t = 0.f;
        #pragma unroll
        for (int i = 0; i < 8; i++) t += sRed[tid][i];
        sInvZ[tid] = 1.f / fmaxf(t, 1e-12f);
    }
    __syncthreads();
    const float invZ0 = sInvZ[0];
    const float invZ1 = sInvZ[1];

    float* xr0 = g_x + (size_t)bn0 * NN;
    for (int m = tid; m < NN; m += 256) {
        float s0 = (sI[0][0][m] + sI[0][1][m]) + (sI[0][2][m] + sI[0][3][m]);
        float s1 = (sI[1][0][m] + sI[1][1][m]) + (sI[1][2][m] + sI[1][3][m]);
        xr0[m]      = 1.f - s0 * invZ0;
        xr0[NN + m] = 1.f - s1 * invZ1;
    }
}

// ---------------------------------------------------------------------------
// Kernel B: 8 elements per thread, j-outer. Weights stored un-duplicated as
// float2 (ws,wc) -> LDS.64; the (w,w) f32x2 operands are built with register
// movs (ALU pipe), halving L1 weight traffic vs LDS.128 duplicated.
// ---------------------------------------------------------------------------
__global__ __launch_bounds__(256, 2)
void embed_proj_kernel(const float* __restrict__ pw,   // (H,16)
                       const float* __restrict__ pb,   // (H)
                       float* __restrict__ out)        // (B,H,N,N)
{
    __shared__ float2 sWf[8][NH];               // [j][h] = (ws, wc)
    __shared__ unsigned long long sBb[NH];      // (b,b)

    const int tid = threadIdx.x;
    if (tid < 8 * NH) {
        int j = tid >> 3, h = tid & 7;
        sWf[j][h] = make_float2(pw[h * 16 + 2 * j + 0], pw[h * 16 + 2 * j + 1]);
    }
    if (tid < NH) sBb[tid] = pack2(pb[tid], pb[tid]);
    __syncthreads();

    const int b = blockIdx.y;
    const int r8 = (blockIdx.x * 256 + tid) * 8;
    if (r8 >= NN2) return;   // NN2 % 8 == 0

    const float4* xp = reinterpret_cast<const float4*>(g_x + (size_t)b * NN2 + r8);
    float4 xa = xp[0], xb = xp[1];
    const float xs[8] = {xa.x, xa.y, xa.z, xa.w, xb.x, xb.y, xb.z, xb.w};

    unsigned long long acc[NH][4];
    #pragma unroll
    for (int h = 0; h < NH; h++) {
        unsigned long long bb = sBb[h];
        #pragma unroll
        for (int p = 0; p < 4; p++) acc[h][p] = bb;
    }

    // 100 / 10000^(j/8)
    const float SCJ[8] = {100.f, 31.622776601683793f, 10.f, 3.1622776601683795f,
                          1.f, 0.31622776601683794f, 0.1f, 0.031622776601683794f};

    #pragma unroll
    for (int j = 0; j < 8; j++) {
        unsigned long long fs[4], fc[4];
        #pragma unroll
        for (int p = 0; p < 4; p++) {
            float t0 = xs[2 * p + 0] * SCJ[j];
            float t1 = xs[2 * p + 1] * SCJ[j];
            fs[p] = pack2(fast_sin(t0), fast_sin(t1));
            fc[p] = pack2(fast_cos(t0), fast_cos(t1));
        }
        #pragma unroll
        for (int h = 0; h < NH; h++) {
            float2 wv = sWf[j][h];                 // LDS.64
            unsigned long long wsd = pack2(wv.x, wv.x);   // ALU movs
            unsigned long long wcd = pack2(wv.y, wv.y);
            #pragma unroll
            for (int p = 0; p < 4; p++) {
                acc[h][p] = fma2(fs[p], wsd, acc[h][p]);
                acc[h][p] = fma2(fc[p], wcd, acc[h][p]);
            }
        }
    }

    float* ob = out + ((size_t)b * NH) * NN2 + r8;
    #pragma unroll
    for (int h = 0; h < NH; h++) {
        float2 o0 = unpack2(acc[h][0]);
        float2 o1 = unpack2(acc[h][1]);
        float2 o2 = unpack2(acc[h][2]);
        float2 o3 = unpack2(acc[h][3]);
        float4 v0 = make_float4(fmaxf(o0.x, 0.f), fmaxf(o0.y, 0.f),
                                fmaxf(o1.x, 0.f), fmaxf(o1.y, 0.f));
        float4 v1 = make_float4(fmaxf(o2.x, 0.f), fmaxf(o2.y, 0.f),
                                fmaxf(o3.x, 0.f), fmaxf(o3.y, 0.f));
        float4* dst = reinterpret_cast<float4*>(ob + (size_t)h * NN2);
        dst[0] = v0;
        dst[1] = v1;
    }
}

extern "C" void kernel_launch(void* const* d_in, const int* in_sizes, int n_in,
                              void* d_out, int out_size) {
    const float* queries = (const float*)d_in[0];
    const float* cur_ref = (const float*)d_in[1];
    // d_in[2] = prev_ref_points — unused by the reference
    const float* vote_w  = (const float*)d_in[3];
    const float* vote_b  = (const float*)d_in[4];
    const float* proj_w  = (const float*)d_in[5];
    const float* proj_b  = (const float*)d_in[6];
    float* out = (float*)d_out;

    hough_row2_kernel<<<NB * NN / 2, 256>>>(queries, cur_ref, vote_w, vote_b);

    dim3 gridB((NN2 / 8 + 255) / 256, NB);
    embed_proj_kernel<<<gridB, 256>>>(proj_w, proj_b, out);
}

// round 8
// speedup vs baseline: 1.9649x; 1.0910x over previous
#include <cuda_runtime.h>

#define NB 4
#define NN 900
#define ND 256
#define NV 16
#define NH 8
#define NN2 (NN * NN)

// scratch: x = 1 - imap/Z, laid out (B,N,N) contiguous
__device__ float g_x[NB * NN2];

__device__ __forceinline__ float fast_ex2(float x) {
    float r; asm("ex2.approx.ftz.f32 %0, %1;" : "=f"(r) : "f"(x)); return r;
}
__device__ __forceinline__ float fast_sin(float x) {
    float r; asm("sin.approx.ftz.f32 %0, %1;" : "=f"(r) : "f"(x)); return r;
}
__device__ __forceinline__ float fast_cos(float x) {
    float r; asm("cos.approx.ftz.f32 %0, %1;" : "=f"(r) : "f"(x)); return r;
}
__device__ __forceinline__ unsigned long long pack2(float a, float b) {
    unsigned long long r;
    asm("mov.b64 %0, {%1, %2};" : "=l"(r)
        : "r"(__float_as_uint(a)), "r"(__float_as_uint(b)));
    return r;
}
__device__ __forceinline__ float2 unpack2(unsigned long long v) {
    unsigned int lo, hi;
    asm("mov.b64 {%0, %1}, %2;" : "=r"(lo), "=r"(hi) : "l"(v));
    return make_float2(__uint_as_float(lo), __uint_as_float(hi));
}
__device__ __forceinline__ unsigned long long fma2(unsigned long long a,
                                                   unsigned long long b,
                                                   unsigned long long c) {
    unsigned long long d;
    asm("fma.rn.f32x2 %0, %1, %2, %3;" : "=l"(d) : "l"(a), "l"(b), "l"(c));
    return d;
}

// ---------------------------------------------------------------------------
// Kernel A: TWO rows (n0, n0+1) per block. Shared sC / barriers / GEMM weight
// loads amortized across both rows; cc reused for both rows' vote evals.
// 4 vote-groups of 64 threads; each group: 4 votes x 2 rows.
// ---------------------------------------------------------------------------
__global__ __launch_bounds__(256, 4)
void hough_row2_kernel(const float* __restrict__ q,     // (B,N,D)
                       const float* __restrict__ cur,   // (B,N,4)
                       const float* __restrict__ vw,    // (32,D)
                       const float* __restrict__ vb)    // (32)
{
    const int pair = blockIdx.x;          // 0 .. NB*NN/2-1
    const int b    = pair / (NN / 2);
    const int n0   = (pair % (NN / 2)) * 2;
    const int bn0  = b * NN + n0;
    const int tid  = threadIdx.x;
    const int lane = tid & 31;
    const int w    = tid >> 5;
    const int g    = tid >> 6;            // vote group 0..3
    const int tg   = tid & 63;

    __shared__ float4 sq4[2][ND / 4];
    __shared__ float2 sC[NN];
    __shared__ float  sI[2][4][NN];
    __shared__ float4 sCoef[2][NV];       // (Ax, Ay, Ni, C0)
    __shared__ float  sVotes[2][2 * NV];
    __shared__ float  sRed[2][8];
    __shared__ float  sInvZ[2];

    if (tid < 128) {
        int r = tid >> 6, i = tid & 63;
        sq4[r][i] = *reinterpret_cast<const float4*>(q + (bn0 + r) * ND + i * 4);
    }
    for (int j = tid; j < NN; j += 256) {
        float4 c4 = *reinterpret_cast<const float4*>(cur + (b * NN + j) * 4);
        sC[j] = make_float2(c4.x, c4.y);
    }
    __syncthreads();

    // votes for BOTH rows: weight vectors loaded once, used with both q rows
    {
        const int k0 = w * 4;
        const float4* w0 = reinterpret_cast<const float4*>(vw + (k0 + 0) * ND);
        const float4* w1 = reinterpret_cast<const float4*>(vw + (k0 + 1) * ND);
        const float4* w2 = reinterpret_cast<const float4*>(vw + (k0 + 2) * ND);
        const float4* w3 = reinterpret_cast<const float4*>(vw + (k0 + 3) * ND);
        float a0 = 0.f, a1 = 0.f, a2 = 0.f, a3 = 0.f;
        float b0 = 0.f, b1 = 0.f, b2 = 0.f, b3 = 0.f;
        #pragma unroll
        for (int i = 0; i < 2; i++) {
            int d = lane + 32 * i;
            float4 qa = sq4[0][d];
            float4 qb = sq4[1][d];
            float4 v0 = __ldg(w0 + d);
            float4 v1 = __ldg(w1 + d);
            float4 v2 = __ldg(w2 + d);
            float4 v3 = __ldg(w3 + d);
            a0 = fmaf(qa.x, v0.x, fmaf(qa.y, v0.y, fmaf(qa.z, v0.z, fmaf(qa.w, v0.w, a0))));
            a1 = fmaf(qa.x, v1.x, fmaf(qa.y, v1.y, fmaf(qa.z, v1.z, fmaf(qa.w, v1.w, a1))));
            a2 = fmaf(qa.x, v2.x, fmaf(qa.y, v2.y, fmaf(qa.z, v2.z, fmaf(qa.w, v2.w, a2))));
            a3 = fmaf(qa.x, v3.x, fmaf(qa.y, v3.y, fmaf(qa.z, v3.z, fmaf(qa.w, v3.w, a3))));
            b0 = fmaf(qb.x, v0.x, fmaf(qb.y, v0.y, fmaf(qb.z, v0.z, fmaf(qb.w, v0.w, b0))));
            b1 = fmaf(qb.x, v1.x, fmaf(qb.y, v1.y, fmaf(qb.z, v1.z, fmaf(qb.w, v1.w, b1))));
            b2 = fmaf(qb.x, v2.x, fmaf(qb.y, v2.y, fmaf(qb.z, v2.z, fmaf(qb.w, v2.w, b2))));
            b3 = fmaf(qb.x, v3.x, fmaf(qb.y, v3.y, fmaf(qb.z, v3.z, fmaf(qb.w, v3.w, b3))));
        }
        #pragma unroll
        for (int o = 16; o; o >>= 1) {
            a0 += __shfl_down_sync(0xffffffffu, a0, o);
            a1 += __shfl_down_sync(0xffffffffu, a1, o);
            a2 += __shfl_down_sync(0xffffffffu, a2, o);
            a3 += __shfl_down_sync(0xffffffffu, a3, o);
            b0 += __shfl_down_sync(0xffffffffu, b0, o);
            b1 += __shfl_down_sync(0xffffffffu, b1, o);
            b2 += __shfl_down_sync(0xffffffffu, b2, o);
            b3 += __shfl_down_sync(0xffffffffu, b3, o);
        }
        if (lane == 0) {
            sVotes[0][k0 + 0] = a0 + vb[k0 + 0];
            sVotes[0][k0 + 1] = a1 + vb[k0 + 1];
            sVotes[0][k0 + 2] = a2 + vb[k0 + 2];
            sVotes[0][k0 + 3] = a3 + vb[k0 + 3];
            sVotes[1][k0 + 0] = b0 + vb[k0 + 0];
            sVotes[1][k0 + 1] = b1 + vb[k0 + 1];
            sVotes[1][k0 + 2] = b2 + vb[k0 + 2];
            sVotes[1][k0 + 3] = b3 + vb[k0 + 3];
        }
    }
    __syncthreads();

    if (tid < 2 * NV) {
        int r = tid >> 4, v = tid & 15;
        int n = n0 + r, bn = bn0 + r;
        float cx = cur[bn * 4 + 0];
        float cy = cur[bn * 4 + 1];
        float vx = cx + sVotes[r][2 * v + 0];
        float vy = cy + sVotes[r][2 * v + 1];
        // reference quirk: sigma index is (n*V + v) mod N
        int idx  = (n * NV + v) % NN;
        float c2 = cur[(b * NN + idx) * 4 + 2];
        float c3 = cur[(b * NN + idx) * 4 + 3];
        float s  = c2 + c3;   // 4*sigma
        float ninv = -11.541560327111707f / (s * s);   // -8*log2e / s^2
        float vv   = fmaf(vx, vx, vy * vy);
        sCoef[r][v] = make_float4(-2.f * ninv * vx, -2.f * ninv * vy,
                                  ninv, ninv * vv);
    }
    __syncthreads();

    // registerize this group's 4 votes for both rows
    float Ax[2][4], Ay[2][4], Ni[2][4], C0[2][4];
    #pragma unroll
    for (int r = 0; r < 2; r++)
        #pragma unroll
        for (int v = 0; v < 4; v++) {
            float4 c = sCoef[r][g * 4 + v];
            Ax[r][v] = c.x; Ay[r][v] = c.y; Ni[r][v] = c.z; C0[r][v] = c.w;
        }

    float part0 = 0.f, part1 = 0.f;
    for (int m = tg; m < NN; m += 64) {
        float2 c  = sC[m];
        float  cc = fmaf(c.x, c.x, c.y * c.y);
        float acc0, acc1;
        {
            float e0 = fast_ex2(fminf(fmaf(c.x, Ax[0][0], fmaf(c.y, Ay[0][0], fmaf(cc, Ni[0][0], C0[0][0]))), 0.f));
            float e1 = fast_ex2(fminf(fmaf(c.x, Ax[0][1], fmaf(c.y, Ay[0][1], fmaf(cc, Ni[0][1], C0[0][1]))), 0.f));
            float e2 = fast_ex2(fminf(fmaf(c.x, Ax[0][2], fmaf(c.y, Ay[0][2], fmaf(cc, Ni[0][2], C0[0][2]))), 0.f));
            float e3 = fast_ex2(fminf(fmaf(c.x, Ax[0][3], fmaf(c.y, Ay[0][3], fmaf(cc, Ni[0][3], C0[0][3]))), 0.f));
            acc0 = (e0 + e1) + (e2 + e3);
        }
        {
            float e0 = fast_ex2(fminf(fmaf(c.x, Ax[1][0], fmaf(c.y, Ay[1][0], fmaf(cc, Ni[1][0], C0[1][0]))), 0.f));
            float e1 = fast_ex2(fminf(fmaf(c.x, Ax[1][1], fmaf(c.y, Ay[1][1], fmaf(cc, Ni[1][1], C0[1][1]))), 0.f));
            float e2 = fast_ex2(fminf(fmaf(c.x, Ax[1][2], fmaf(c.y, Ay[1][2], fmaf(cc, Ni[1][2], C0[1][2]))), 0.f));
            float e3 = fast_ex2(fminf(fmaf(c.x, Ax[1][3], fmaf(c.y, Ay[1][3], fmaf(cc, Ni[1][3], C0[1][3]))), 0.f));
            acc1 = (e0 + e1) + (e2 + e3);
        }
        sI[0][g][m] = acc0;
        sI[1][g][m] = acc1;
        part0 += acc0;
        part1 += acc1;
    }
    #pragma unroll
    for (int o = 16; o; o >>= 1) {
        part0 += __shfl_down_sync(0xffffffffu, part0, o);
        part1 += __shfl_down_sync(0xffffffffu, part1, o);
    }
    if (lane == 0) { sRed[0][w] = part0; sRed[1][w] = part1; }
    __syncthreads();
    if (tid < 2) {
        float t = 0.f;
        #pragma unroll
        for (int i = 0; i < 8; i++) t += sRed[tid][i];
        sInvZ[tid] = 1.f / fmaxf(t, 1e-12f);
    }
    __syncthreads();
    const float invZ0 = sInvZ[0];
    const float invZ1 = sInvZ[1];

    float* xr0 = g_x + (size_t)bn0 * NN;
    for (int m = tid; m < NN; m += 256) {
        float s0 = (sI[0][0][m] + sI[0][1][m]) + (sI[0][2][m] + sI[0][3][m]);
        float s1 = (sI[1][0][m] + sI[1][1][m]) + (sI[1][2][m] + sI[1][3][m]);
        xr0[m]      = 1.f - s0 * invZ0;
        xr0[NN + m] = 1.f - s1 * invZ1;
    }
}

// ---------------------------------------------------------------------------
// Kernel B: 4 elements per thread (2 f32x2 pairs), j-outer, acc[8][2] in
// registers (~half the register file of the 8-elem variant) -> 3 CTAs/SM.
// Weights un-duplicated float2 (LDS.64) + ALU dup movs.
// ---------------------------------------------------------------------------
__global__ __launch_bounds__(256, 3)
void embed_proj_kernel(const float* __restrict__ pw,   // (H,16)
                       const float* __restrict__ pb,   // (H)
                       float* __restrict__ out)        // (B,H,N,N)
{
    __shared__ float2 sWf[8][NH];               // [j][h] = (ws, wc)
    __shared__ unsigned long long sBb[NH];      // (b,b)

    const int tid = threadIdx.x;
    if (tid < 8 * NH) {
        int j = tid >> 3, h = tid & 7;
        sWf[j][h] = make_float2(pw[h * 16 + 2 * j + 0], pw[h * 16 + 2 * j + 1]);
    }
    if (tid < NH) sBb[tid] = pack2(pb[tid], pb[tid]);
    __syncthreads();

    const int b = blockIdx.y;
    const int r4 = (blockIdx.x * 256 + tid) * 4;
    if (r4 >= NN2) return;   // NN2 % 4 == 0

    const float4 xv = *reinterpret_cast<const float4*>(g_x + (size_t)b * NN2 + r4);

    unsigned long long acc[NH][2];
    #pragma unroll
    for (int h = 0; h < NH; h++) {
        unsigned long long bb = sBb[h];
        acc[h][0] = bb;
        acc[h][1] = bb;
    }

    // 100 / 10000^(j/8)
    const float SCJ[8] = {100.f, 31.622776601683793f, 10.f, 3.1622776601683795f,
                          1.f, 0.31622776601683794f, 0.1f, 0.031622776601683794f};

    #pragma unroll
    for (int j = 0; j < 8; j++) {
        float t0 = xv.x * SCJ[j];
        float t1 = xv.y * SCJ[j];
        float t2 = xv.z * SCJ[j];
        float t3 = xv.w * SCJ[j];
        unsigned long long fs0 = pack2(fast_sin(t0), fast_sin(t1));
        unsigned long long fs1 = pack2(fast_sin(t2), fast_sin(t3));
        unsigned long long fc0 = pack2(fast_cos(t0), fast_cos(t1));
        unsigned long long fc1 = pack2(fast_cos(t2), fast_cos(t3));
        #pragma unroll
        for (int h = 0; h < NH; h++) {
            float2 wv = sWf[j][h];                        // LDS.64
            unsigned long long wsd = pack2(wv.x, wv.x);   // ALU dup
            unsigned long long wcd = pack2(wv.y, wv.y);
            acc[h][0] = fma2(fs0, wsd, acc[h][0]);
            acc[h][1] = fma2(fs1, wsd, acc[h][1]);
            acc[h][0] = fma2(fc0, wcd, acc[h][0]);
            acc[h][1] = fma2(fc1, wcd, acc[h][1]);
        }
    }

    float* ob = out + ((size_t)b * NH) * NN2 + r4;
    #pragma unroll
    for (int h = 0; h < NH; h++) {
        float2 o0 = unpack2(acc[h][0]);
        float2 o1 = unpack2(acc[h][1]);
        float4 v = make_float4(fmaxf(o0.x, 0.f), fmaxf(o0.y, 0.f),
                               fmaxf(o1.x, 0.f), fmaxf(o1.y, 0.f));
        *reinterpret_cast<float4*>(ob + (size_t)h * NN2) = v;
    }
}

extern "C" void kernel_launch(void* const* d_in, const int* in_sizes, int n_in,
                              void* d_out, int out_size) {
    const float* queries = (const float*)d_in[0];
    const float* cur_ref = (const float*)d_in[1];
    // d_in[2] = prev_ref_points — unused by the reference
    const float* vote_w  = (const float*)d_in[3];
    const float* vote_b  = (const float*)d_in[4];
    const float* proj_w  = (const float*)d_in[5];
    const float* proj_b  = (const float*)d_in[6];
    float* out = (float*)d_out;

    hough_row2_kernel<<<NB * NN / 2, 256>>>(queries, cur_ref, vote_w, vote_b);

    dim3 gridB((NN2 / 4 + 255) / 256, NB);
    embed_proj_kernel<<<gridB, 256>>>(proj_w, proj_b, out);
}